// round 6
// baseline (speedup 1.0000x reference)
#include <cuda_runtime.h>
#include <cuda_fp16.h>
#include <cstdint>

// Problem dims (fixed)
#define NB   32
#define SEQ  2048
#define DIM  400
#define HID  512
#define MROWS (NB * SEQ)          // 65536
#define LN_EPS 1e-5f
#define SOFTMAX_SCALE 0.04419417382415922f  // 1/sqrt(512)

// ---------------------------------------------------------------------------
// Scratch (device globals — allocation-free per harness rules)
// ---------------------------------------------------------------------------
__device__ __half g_q[(size_t)MROWS * HID];          // 64 MB (pre-scaled by 1/sqrt(512))
__device__ __half g_k[(size_t)MROWS * HID];          // 64 MB
__device__ __half g_v[(size_t)MROWS * HID];          // 64 MB
__device__ __half g_o[(size_t)MROWS * HID];          // 64 MB
__device__ float  g_s[(size_t)NB * SEQ * SEQ];       // 512 MB  scores fp32 (single-use stream)
__device__ __half g_p[(size_t)NB * SEQ * SEQ];       // 256 MB  probs fp16  (single-use stream)
__device__ float  g_proj[(size_t)MROWS * DIM];       // 104 MB  (single-use stream)
__device__ __half g_wq[DIM * HID];
__device__ __half g_wk[DIM * HID];
__device__ __half g_wv[DIM * HID];
__device__ __half g_wp[HID * DIM];

// ---------------------------------------------------------------------------
// MMA / ldmatrix / cp.async helpers
// ---------------------------------------------------------------------------
__device__ __forceinline__ uint32_t cvta_s(const void* p) {
    return (uint32_t)__cvta_generic_to_shared(p);
}

__device__ __forceinline__ void ldsm4(uint32_t* r, uint32_t a) {
    asm volatile("ldmatrix.sync.aligned.m8n8.x4.shared.b16 {%0,%1,%2,%3}, [%4];\n"
                 : "=r"(r[0]), "=r"(r[1]), "=r"(r[2]), "=r"(r[3]) : "r"(a));
}
__device__ __forceinline__ void ldsm4t(uint32_t* r, uint32_t a) {
    asm volatile("ldmatrix.sync.aligned.m8n8.x4.trans.shared.b16 {%0,%1,%2,%3}, [%4];\n"
                 : "=r"(r[0]), "=r"(r[1]), "=r"(r[2]), "=r"(r[3]) : "r"(a));
}
__device__ __forceinline__ void mma16816(float* c, const uint32_t* a, const uint32_t* b) {
    asm volatile(
        "mma.sync.aligned.m16n8k16.row.col.f32.f16.f16.f32 "
        "{%0,%1,%2,%3}, {%4,%5,%6,%7}, {%8,%9}, {%0,%1,%2,%3};\n"
        : "+f"(c[0]), "+f"(c[1]), "+f"(c[2]), "+f"(c[3])
        : "r"(a[0]), "r"(a[1]), "r"(a[2]), "r"(a[3]), "r"(b[0]), "r"(b[1]));
}

__device__ __forceinline__ void cp16(uint32_t dst, const void* src) {
    asm volatile("cp.async.cg.shared.global [%0], [%1], 16;\n" :: "r"(dst), "l"(src));
}
__device__ __forceinline__ void cp_commit() {
    asm volatile("cp.async.commit_group;\n" ::: "memory");
}
template <int N>
__device__ __forceinline__ void cp_wait() {
    asm volatile("cp.async.wait_group %0;\n" :: "n"(N) : "memory");
}

__device__ __forceinline__ float warp_sum(float v) {
    #pragma unroll
    for (int o = 16; o; o >>= 1) v += __shfl_xor_sync(0xffffffffu, v, o);
    return v;
}
__device__ __forceinline__ float warp_max(float v) {
    #pragma unroll
    for (int o = 16; o; o >>= 1) v = fmaxf(v, __shfl_xor_sync(0xffffffffu, v, o));
    return v;
}

// ---------------------------------------------------------------------------
// Kernel 0: pack weights fp32 -> fp16
// ---------------------------------------------------------------------------
__global__ void pack_w_kernel(const float* __restrict__ wq, const float* __restrict__ wk,
                              const float* __restrict__ wv, const float* __restrict__ wp) {
    const int NW = DIM * HID;  // 204800 (same count for wp)
    int i = blockIdx.x * blockDim.x + threadIdx.x;
    if (i < NW)               g_wq[i]          = __float2half_rn(wq[i]);
    else if (i < 2 * NW)      g_wk[i - NW]     = __float2half_rn(wk[i - NW]);
    else if (i < 3 * NW)      g_wv[i - 2 * NW] = __float2half_rn(wv[i - 2 * NW]);
    else if (i < 4 * NW)      g_wp[i - 3 * NW] = __float2half_rn(wp[i - 3 * NW]);
}

// ---------------------------------------------------------------------------
// Kernel 1: QKV projections.  C[65536,512] = A[65536,400] * W[400,512] + b
// grid (512, 4, 3): z=0 -> q (rgb), z=1 -> k (pose), z=2 -> v (pose)
// Block tile 128x128, BK=32, 8 warps (4x2), warp tile 32x64.
// q output is pre-scaled by 1/sqrt(512) (folded out of scores epilogue).
// ---------------------------------------------------------------------------
__global__ __launch_bounds__(256) void qkv_kernel(
    const float* __restrict__ rgb, const float* __restrict__ pose,
    const float* __restrict__ bq, const float* __restrict__ bk,
    const float* __restrict__ bv) {
    const int z = blockIdx.z;
    const float*  A    = (z == 0) ? rgb : pose;
    const __half* W    = (z == 0) ? g_wq : (z == 1) ? g_wk : g_wv;
    const float*  bias = (z == 0) ? bq : (z == 1) ? bk : bv;
    __half*       dst  = (z == 0) ? g_q : (z == 1) ? g_k : g_v;
    const float   osc  = (z == 0) ? SOFTMAX_SCALE : 1.0f;

    const int m0 = blockIdx.x * 128, n0 = blockIdx.y * 128;
    __shared__ __half As[128][40];   // row-major [M][K], pad 8
    __shared__ __half Bs[32][136];   // [K][N] trans path, pad 8

    const int tid = threadIdx.x, lane = tid & 31, warp = tid >> 5;
    const int wm = warp & 3, wn = warp >> 2;        // warp tile 32 x 64
    const int br = tid >> 4, bc = (tid & 15) * 8;   // B loader: 16 rows/pass x 128 cols

    float acc[2][8][4];
    #pragma unroll
    for (int i = 0; i < 2; i++)
        #pragma unroll
        for (int j = 0; j < 8; j++)
            #pragma unroll
            for (int l = 0; l < 4; l++) acc[i][j][l] = 0.f;

    for (int k0 = 0; k0 < DIM; k0 += 32) {
        // A: 128x32 fp32 -> fp16 smem (4 float4 / thread)
        #pragma unroll
        for (int t = 0; t < 4; t++) {
            int i = tid + t * 256;
            int r = i >> 3, c4 = i & 7;
            int gk = k0 + c4 * 4;
            float4 val = make_float4(0.f, 0.f, 0.f, 0.f);
            if (gk < DIM) val = *(const float4*)(A + (size_t)(m0 + r) * DIM + gk);
            __half2* sp = (__half2*)&As[r][c4 * 4];
            sp[0] = __floats2half2_rn(val.x, val.y);
            sp[1] = __floats2half2_rn(val.z, val.w);
        }
        // B: 32x128 fp16 (2 uint4 / thread), zero-fill K rows >= DIM
        #pragma unroll
        for (int t = 0; t < 2; t++) {
            int r = br + t * 16;
            int gk = k0 + r;
            uint4 val = make_uint4(0, 0, 0, 0);
            if (gk < DIM) val = *(const uint4*)(W + (size_t)gk * HID + n0 + bc);
            *(uint4*)&Bs[r][bc] = val;
        }
        __syncthreads();

        #pragma unroll
        for (int ks = 0; ks < 32; ks += 16) {
            uint32_t af[2][4], bf[4][4];
            #pragma unroll
            for (int mt = 0; mt < 2; mt++)
                ldsm4(af[mt], cvta_s(&As[wm * 32 + mt * 16 + (lane & 15)][ks + (lane >> 4) * 8]));
            #pragma unroll
            for (int np = 0; np < 4; np++)
                ldsm4t(bf[np], cvta_s(&Bs[ks + (lane & 15)][wn * 64 + np * 16 + (lane >> 4) * 8]));
            #pragma unroll
            for (int mt = 0; mt < 2; mt++)
                #pragma unroll
                for (int nt = 0; nt < 8; nt++)
                    mma16816(acc[mt][nt], af[mt], &bf[nt >> 1][(nt & 1) * 2]);
        }
        __syncthreads();
    }

    // Epilogue: (+bias) * osc, convert, store fp16
    const int row0 = m0 + wm * 32, col0 = n0 + wn * 64;
    #pragma unroll
    for (int mt = 0; mt < 2; mt++)
        #pragma unroll
        for (int nt = 0; nt < 8; nt++) {
            int r = row0 + mt * 16 + (lane >> 2);
            int c = col0 + nt * 8 + (lane & 3) * 2;
            float b0 = bias[c], b1 = bias[c + 1];
            *(__half2*)(dst + (size_t)r * HID + c) =
                __floats2half2_rn((acc[mt][nt][0] + b0) * osc, (acc[mt][nt][1] + b1) * osc);
            *(__half2*)(dst + (size_t)(r + 8) * HID + c) =
                __floats2half2_rn((acc[mt][nt][2] + b0) * osc, (acc[mt][nt][3] + b1) * osc);
        }
}

// ---------------------------------------------------------------------------
// Kernel 2: scores.  S[b] = Q[b] * K[b]^T (q pre-scaled).  M=N=2048, K=512.
// grid (16, 16, 32). Block 128x128, BK=32, 8 warps (4x2), warp tile 32x64.
// 2-stage cp.async double buffering. S writes streamed (evict-first).
// ---------------------------------------------------------------------------
__global__ __launch_bounds__(256) void scores_kernel() {
    const int b = blockIdx.z;
    const int m0 = blockIdx.x * 128, n0 = blockIdx.y * 128;
    const __half* Q = g_q + (size_t)b * SEQ * HID;
    const __half* K = g_k + (size_t)b * SEQ * HID;
    float* S = g_s + (size_t)b * SEQ * SEQ;

    __shared__ __half As[2][128][40];  // [M][K]
    __shared__ __half Bs[2][128][40];  // [N][K]  (non-trans ldmatrix path)

    const int tid = threadIdx.x, lane = tid & 31, warp = tid >> 5;
    const int wm = warp & 3, wn = warp >> 2;  // warp tile 32 x 64
    const int lr = tid >> 2, lc = (tid & 3) * 8;  // loader coords: 64 rows/pass x 32 cols

    float acc[2][8][4];
    #pragma unroll
    for (int i = 0; i < 2; i++)
        #pragma unroll
        for (int j = 0; j < 8; j++)
            #pragma unroll
            for (int l = 0; l < 4; l++) acc[i][j][l] = 0.f;

    const int KT = HID / 32;  // 16 k-steps

    // Prefetch stage 0
    #pragma unroll
    for (int t = 0; t < 2; t++) {
        int r = lr + t * 64;
        cp16(cvta_s(&As[0][r][lc]), Q + (size_t)(m0 + r) * HID + lc);
        cp16(cvta_s(&Bs[0][r][lc]), K + (size_t)(n0 + r) * HID + lc);
    }
    cp_commit();

    for (int kt = 0; kt < KT; kt++) {
        const int buf = kt & 1;
        if (kt + 1 < KT) {
            const int k0 = (kt + 1) * 32;
            #pragma unroll
            for (int t = 0; t < 2; t++) {
                int r = lr + t * 64;
                cp16(cvta_s(&As[buf ^ 1][r][lc]), Q + (size_t)(m0 + r) * HID + k0 + lc);
                cp16(cvta_s(&Bs[buf ^ 1][r][lc]), K + (size_t)(n0 + r) * HID + k0 + lc);
            }
            cp_commit();
            cp_wait<1>();
        } else {
            cp_wait<0>();
        }
        __syncthreads();

        #pragma unroll
        for (int ks = 0; ks < 32; ks += 16) {
            uint32_t af[2][4], bf[4][4];
            #pragma unroll
            for (int mt = 0; mt < 2; mt++)
                ldsm4(af[mt], cvta_s(&As[buf][wm * 32 + mt * 16 + (lane & 15)][ks + (lane >> 4) * 8]));
            #pragma unroll
            for (int np = 0; np < 4; np++) {  // two n8 tiles per x4 (non-trans, rows=n)
                int n = wn * 64 + np * 16 + (lane & 7) + ((lane >> 4) << 3);
                int k = ks + ((lane >> 3) & 1) * 8;
                ldsm4(bf[np], cvta_s(&Bs[buf][n][k]));
            }
            #pragma unroll
            for (int mt = 0; mt < 2; mt++)
                #pragma unroll
                for (int nt = 0; nt < 8; nt++)
                    mma16816(acc[mt][nt], af[mt], &bf[nt >> 1][(nt & 1) * 2]);
        }
        __syncthreads();
    }

    const int row0 = m0 + wm * 32, col0 = n0 + wn * 64;
    #pragma unroll
    for (int mt = 0; mt < 2; mt++)
        #pragma unroll
        for (int nt = 0; nt < 8; nt++) {
            int r = row0 + mt * 16 + (lane >> 2);
            int c = col0 + nt * 8 + (lane & 3) * 2;
            __stcs((float2*)(S + (size_t)r * SEQ + c),
                   make_float2(acc[mt][nt][0], acc[mt][nt][1]));
            __stcs((float2*)(S + (size_t)(r + 8) * SEQ + c),
                   make_float2(acc[mt][nt][2], acc[mt][nt][3]));
        }
}

// ---------------------------------------------------------------------------
// Kernel 3: row softmax (one warp per row of 2048), write fp16 probs
// Streaming loads/stores — S and P are single-use, don't pollute L2.
// ---------------------------------------------------------------------------
__global__ __launch_bounds__(256) void softmax_kernel() {
    const int row = blockIdx.x * 8 + (threadIdx.x >> 5);
    const int lane = threadIdx.x & 31;
    const float4* s = (const float4*)(g_s + (size_t)row * SEQ);

    float v[64];
    float mx = -1e30f;
    #pragma unroll
    for (int i = 0; i < 16; i++) {
        float4 f = __ldcs(s + lane + i * 32);
        v[4 * i + 0] = f.x; v[4 * i + 1] = f.y; v[4 * i + 2] = f.z; v[4 * i + 3] = f.w;
        mx = fmaxf(mx, fmaxf(fmaxf(f.x, f.y), fmaxf(f.z, f.w)));
    }
    mx = warp_max(mx);
    float sum = 0.f;
    #pragma unroll
    for (int i = 0; i < 64; i++) { v[i] = __expf(v[i] - mx); sum += v[i]; }
    sum = warp_sum(sum);
    const float inv = 1.0f / sum;

    float* p = (float*)(g_p + (size_t)row * SEQ);  // store half2 pairs as float bits
    #pragma unroll
    for (int i = 0; i < 16; i++) {
        int idx = lane + i * 32;
        __half2 h0 = __floats2half2_rn(v[4 * i + 0] * inv, v[4 * i + 1] * inv);
        __half2 h1 = __floats2half2_rn(v[4 * i + 2] * inv, v[4 * i + 3] * inv);
        __stcs(p + idx * 2 + 0, __uint_as_float(*(uint32_t*)&h0));
        __stcs(p + idx * 2 + 1, __uint_as_float(*(uint32_t*)&h1));
    }
}

// ---------------------------------------------------------------------------
// Kernel 4: O[b] = P[b] * V[b].  M=2048, N=512, K=2048.
// grid (16, 4, 32). Block 128x128, BK=32, 8 warps (4x2), warp tile 32x64.
// 2-stage cp.async double buffering (37.9 KB smem).
// ---------------------------------------------------------------------------
__global__ __launch_bounds__(256) void pv_kernel() {
    const int b = blockIdx.z;
    const int m0 = blockIdx.x * 128, n0 = blockIdx.y * 128;
    const __half* P = g_p + (size_t)b * SEQ * SEQ;
    const __half* V = g_v + (size_t)b * SEQ * HID;
    __half* O = g_o + (size_t)b * SEQ * HID;

    __shared__ __half As[2][128][40];   // [M][K]
    __shared__ __half Bs[2][32][136];   // [K][N] trans path, pad 8

    const int tid = threadIdx.x, lane = tid & 31, warp = tid >> 5;
    const int wm = warp & 3, wn = warp >> 2;           // warp tile 32 x 64
    const int lr = tid >> 2, lc = (tid & 3) * 8;        // A loader: 64 rows/pass x 32 cols
    const int br = tid >> 4, bc = (tid & 15) * 8;       // B loader: 16 rows/pass x 128 cols

    float acc[2][8][4];
    #pragma unroll
    for (int i = 0; i < 2; i++)
        #pragma unroll
        for (int j = 0; j < 8; j++)
            #pragma unroll
            for (int l = 0; l < 4; l++) acc[i][j][l] = 0.f;

    const int KT = SEQ / 32;  // 64 k-steps

    // Prefetch stage 0
    #pragma unroll
    for (int t = 0; t < 2; t++) {
        int r = lr + t * 64;
        cp16(cvta_s(&As[0][r][lc]), P + (size_t)(m0 + r) * SEQ + lc);
    }
    #pragma unroll
    for (int t = 0; t < 2; t++) {
        int r = br + t * 16;
        cp16(cvta_s(&Bs[0][r][bc]), V + (size_t)r * HID + n0 + bc);
    }
    cp_commit();

    for (int kt = 0; kt < KT; kt++) {
        const int buf = kt & 1;
        if (kt + 1 < KT) {
            const int k0 = (kt + 1) * 32;
            #pragma unroll
            for (int t = 0; t < 2; t++) {
                int r = lr + t * 64;
                cp16(cvta_s(&As[buf ^ 1][r][lc]), P + (size_t)(m0 + r) * SEQ + k0 + lc);
            }
            #pragma unroll
            for (int t = 0; t < 2; t++) {
                int r = br + t * 16;
                cp16(cvta_s(&Bs[buf ^ 1][r][bc]), V + (size_t)(k0 + r) * HID + n0 + bc);
            }
            cp_commit();
            cp_wait<1>();
        } else {
            cp_wait<0>();
        }
        __syncthreads();

        #pragma unroll
        for (int ks = 0; ks < 32; ks += 16) {
            uint32_t af[2][4], bf[4][4];
            #pragma unroll
            for (int mt = 0; mt < 2; mt++)
                ldsm4(af[mt], cvta_s(&As[buf][wm * 32 + mt * 16 + (lane & 15)][ks + (lane >> 4) * 8]));
            #pragma unroll
            for (int np = 0; np < 4; np++)
                ldsm4t(bf[np], cvta_s(&Bs[buf][ks + (lane & 15)][wn * 64 + np * 16 + (lane >> 4) * 8]));
            #pragma unroll
            for (int mt = 0; mt < 2; mt++)
                #pragma unroll
                for (int nt = 0; nt < 8; nt++)
                    mma16816(acc[mt][nt], af[mt], &bf[nt >> 1][(nt & 1) * 2]);
        }
        __syncthreads();
    }

    const int row0 = m0 + wm * 32, col0 = n0 + wn * 64;
    #pragma unroll
    for (int mt = 0; mt < 2; mt++)
        #pragma unroll
        for (int nt = 0; nt < 8; nt++) {
            int r = row0 + mt * 16 + (lane >> 2);
            int c = col0 + nt * 8 + (lane & 3) * 2;
            *(__half2*)(O + (size_t)r * HID + c) =
                __floats2half2_rn(acc[mt][nt][0], acc[mt][nt][1]);
            *(__half2*)(O + (size_t)(r + 8) * HID + c) =
                __floats2half2_rn(acc[mt][nt][2], acc[mt][nt][3]);
        }
}

// ---------------------------------------------------------------------------
// Kernel 5: proj = O * Wp + bp.  M=65536, N=400, K=512.
// grid (512, 4). Block 128x128, BK=32, 8 warps (4x2), warp tile 32x64.
// Output streamed (single-use before ln). Guard N < 400.
// ---------------------------------------------------------------------------
__global__ __launch_bounds__(256) void proj_kernel(const float* __restrict__ bp) {
    const int m0 = blockIdx.x * 128, n0 = blockIdx.y * 128;

    __shared__ __half As[128][40];
    __shared__ __half Bs[32][136];

    const int tid = threadIdx.x, lane = tid & 31, warp = tid >> 5;
    const int wm = warp & 3, wn = warp >> 2;        // warp tile 32 x 64
    const int br = tid >> 4, bc = (tid & 15) * 8;   // B loader: 16 rows/pass x 128 cols

    float acc[2][8][4];
    #pragma unroll
    for (int i = 0; i < 2; i++)
        #pragma unroll
        for (int j = 0; j < 8; j++)
            #pragma unroll
            for (int l = 0; l < 4; l++) acc[i][j][l] = 0.f;

    for (int k0 = 0; k0 < HID; k0 += 32) {
        #pragma unroll
        for (int t = 0; t < 2; t++) {
            int i = tid + t * 256;
            int r = i >> 2, c = (i & 3) * 8;
            *(uint4*)&As[r][c] = *(const uint4*)(g_o + (size_t)(m0 + r) * HID + k0 + c);
        }
        #pragma unroll
        for (int t = 0; t < 2; t++) {
            int r = br + t * 16;
            int n = n0 + bc;
            uint4 val = make_uint4(0, 0, 0, 0);
            if (n < DIM) val = *(const uint4*)(g_wp + (size_t)(k0 + r) * DIM + n);
            *(uint4*)&Bs[r][bc] = val;
        }
        __syncthreads();

        #pragma unroll
        for (int ks = 0; ks < 32; ks += 16) {
            uint32_t af[2][4], bf[4][4];
            #pragma unroll
            for (int mt = 0; mt < 2; mt++)
                ldsm4(af[mt], cvta_s(&As[wm * 32 + mt * 16 + (lane & 15)][ks + (lane >> 4) * 8]));
            #pragma unroll
            for (int np = 0; np < 4; np++)
                ldsm4t(bf[np], cvta_s(&Bs[ks + (lane & 15)][wn * 64 + np * 16 + (lane >> 4) * 8]));
            #pragma unroll
            for (int mt = 0; mt < 2; mt++)
                #pragma unroll
                for (int nt = 0; nt < 8; nt++)
                    mma16816(acc[mt][nt], af[mt], &bf[nt >> 1][(nt & 1) * 2]);
        }
        __syncthreads();
    }

    const int row0 = m0 + wm * 32, col0 = n0 + wn * 64;
    #pragma unroll
    for (int mt = 0; mt < 2; mt++)
        #pragma unroll
        for (int nt = 0; nt < 8; nt++) {
            int c = col0 + nt * 8 + (lane & 3) * 2;
            if (c < DIM) {
                int r = row0 + mt * 16 + (lane >> 2);
                float b0 = bp[c], b1 = bp[c + 1];
                __stcs((float2*)(g_proj + (size_t)r * DIM + c),
                       make_float2(acc[mt][nt][0] + b0, acc[mt][nt][1] + b1));
                __stcs((float2*)(g_proj + (size_t)(r + 8) * DIM + c),
                       make_float2(acc[mt][nt][2] + b0, acc[mt][nt][3] + b1));
            }
        }
}

// ---------------------------------------------------------------------------
// Kernel 6: gated residual + LayerNorm over 400.  One warp per row.
// ---------------------------------------------------------------------------
__global__ __launch_bounds__(256) void ln_kernel(
    const float* __restrict__ rgb, const float* __restrict__ gamma,
    const float* __restrict__ beta, const float* __restrict__ gate,
    float* __restrict__ out) {
    const int row = blockIdx.x * 8 + (threadIdx.x >> 5);
    const int lane = threadIdx.x & 31;
    const float gt = gate[0];

    const float4* pr = (const float4*)(g_proj + (size_t)row * DIM);
    const float4* rg = (const float4*)(rgb + (size_t)row * DIM);

    float x[16];
    float sum = 0.f;
    #pragma unroll
    for (int i = 0; i < 4; i++) {
        int idx = lane + i * 32;
        if (idx < 100) {
            float4 p4 = __ldcs(pr + idx);
            float4 r4 = rg[idx];
            x[4 * i + 0] = r4.x + gt * p4.x;
            x[4 * i + 1] = r4.y + gt * p4.y;
            x[4 * i + 2] = r4.z + gt * p4.z;
            x[4 * i + 3] = r4.w + gt * p4.w;
            sum += x[4 * i] + x[4 * i + 1] + x[4 * i + 2] + x[4 * i + 3];
        } else {
            x[4 * i] = x[4 * i + 1] = x[4 * i + 2] = x[4 * i + 3] = 0.f;
        }
    }
    const float mean = warp_sum(sum) * (1.0f / DIM);

    float vs = 0.f;
    #pragma unroll
    for (int i = 0; i < 4; i++) {
        int idx = lane + i * 32;
        if (idx < 100) {
            #pragma unroll
            for (int j = 0; j < 4; j++) {
                float d = x[4 * i + j] - mean;
                vs += d * d;
            }
        }
    }
    const float rstd = rsqrtf(warp_sum(vs) * (1.0f / DIM) + LN_EPS);

    float4* o4 = (float4*)(out + (size_t)row * DIM);
    const float4* g4 = (const float4*)gamma;
    const float4* b4 = (const float4*)beta;
    #pragma unroll
    for (int i = 0; i < 4; i++) {
        int idx = lane + i * 32;
        if (idx < 100) {
            float4 gm = g4[idx], bt = b4[idx];
            float4 r;
            r.x = (x[4 * i + 0] - mean) * rstd * gm.x + bt.x;
            r.y = (x[4 * i + 1] - mean) * rstd * gm.y + bt.y;
            r.z = (x[4 * i + 2] - mean) * rstd * gm.z + bt.z;
            r.w = (x[4 * i + 3] - mean) * rstd * gm.w + bt.w;
            o4[idx] = r;
        }
    }
}

// ---------------------------------------------------------------------------
// Launch
// ---------------------------------------------------------------------------
extern "C" void kernel_launch(void* const* d_in, const int* in_sizes, int n_in,
                              void* d_out, int out_size) {
    (void)in_sizes; (void)n_in; (void)out_size;
    const float* rgb   = (const float*)d_in[0];
    const float* pose  = (const float*)d_in[1];
    const float* Wq    = (const float*)d_in[2];
    const float* bq    = (const float*)d_in[3];
    const float* Wk    = (const float*)d_in[4];
    const float* bk    = (const float*)d_in[5];
    const float* Wv    = (const float*)d_in[6];
    const float* bv    = (const float*)d_in[7];
    const float* Wp    = (const float*)d_in[8];
    const float* bp    = (const float*)d_in[9];
    const float* gamma = (const float*)d_in[10];
    const float* beta  = (const float*)d_in[11];
    const float* gate  = (const float*)d_in[12];
    float* out = (float*)d_out;

    pack_w_kernel<<<(4 * DIM * HID + 255) / 256, 256>>>(Wq, Wk, Wv, Wp);
    qkv_kernel<<<dim3(MROWS / 128, HID / 128, 3), 256>>>(rgb, pose, bq, bk, bv);
    scores_kernel<<<dim3(SEQ / 128, SEQ / 128, NB), 256>>>();
    softmax_kernel<<<MROWS / 8, 256>>>();
    pv_kernel<<<dim3(SEQ / 128, HID / 128, NB), 256>>>();
    proj_kernel<<<dim3(MROWS / 128, (DIM + 127) / 128, 1), 256>>>(bp);
    ln_kernel<<<MROWS / 8, 256>>>(rgb, gamma, beta, gate, out);
}

// round 13
// speedup vs baseline: 1.0254x; 1.0254x over previous
#include <cuda_runtime.h>
#include <cuda_fp16.h>
#include <cstdint>

// Problem dims (fixed)
#define NB   32
#define SEQ  2048
#define DIM  400
#define HID  512
#define MROWS (NB * SEQ)          // 65536
#define LN_EPS 1e-5f
#define SOFTMAX_SCALE 0.04419417382415922f  // 1/sqrt(512)

// ---------------------------------------------------------------------------
// Scratch (device globals — allocation-free per harness rules)
// ---------------------------------------------------------------------------
__device__ __half g_q[(size_t)MROWS * HID];          // 64 MB (pre-scaled by 1/sqrt(512))
__device__ __half g_k[(size_t)MROWS * HID];          // 64 MB
__device__ __half g_v[(size_t)MROWS * HID];          // 64 MB
__device__ __half g_o[(size_t)MROWS * HID];          // 64 MB
__device__ __half g_s[(size_t)NB * SEQ * SEQ];       // 256 MB  scores fp16 (single-use stream)
__device__ __half g_p[(size_t)NB * SEQ * SEQ];       // 256 MB  probs fp16  (single-use stream)
__device__ float  g_proj[(size_t)MROWS * DIM];       // 104 MB  (single-use stream)
__device__ __half g_wq[DIM * HID];
__device__ __half g_wk[DIM * HID];
__device__ __half g_wv[DIM * HID];
__device__ __half g_wp[HID * DIM];

// ---------------------------------------------------------------------------
// MMA / ldmatrix / cp.async helpers
// ---------------------------------------------------------------------------
__device__ __forceinline__ uint32_t cvta_s(const void* p) {
    return (uint32_t)__cvta_generic_to_shared(p);
}

__device__ __forceinline__ void ldsm4(uint32_t* r, uint32_t a) {
    asm volatile("ldmatrix.sync.aligned.m8n8.x4.shared.b16 {%0,%1,%2,%3}, [%4];\n"
                 : "=r"(r[0]), "=r"(r[1]), "=r"(r[2]), "=r"(r[3]) : "r"(a));
}
__device__ __forceinline__ void ldsm4t(uint32_t* r, uint32_t a) {
    asm volatile("ldmatrix.sync.aligned.m8n8.x4.trans.shared.b16 {%0,%1,%2,%3}, [%4];\n"
                 : "=r"(r[0]), "=r"(r[1]), "=r"(r[2]), "=r"(r[3]) : "r"(a));
}
__device__ __forceinline__ void mma16816(float* c, const uint32_t* a, const uint32_t* b) {
    asm volatile(
        "mma.sync.aligned.m16n8k16.row.col.f32.f16.f16.f32 "
        "{%0,%1,%2,%3}, {%4,%5,%6,%7}, {%8,%9}, {%0,%1,%2,%3};\n"
        : "+f"(c[0]), "+f"(c[1]), "+f"(c[2]), "+f"(c[3])
        : "r"(a[0]), "r"(a[1]), "r"(a[2]), "r"(a[3]), "r"(b[0]), "r"(b[1]));
}

__device__ __forceinline__ void cp16(uint32_t dst, const void* src) {
    asm volatile("cp.async.cg.shared.global [%0], [%1], 16;\n" :: "r"(dst), "l"(src));
}
__device__ __forceinline__ void cp_commit() {
    asm volatile("cp.async.commit_group;\n" ::: "memory");
}
template <int N>
__device__ __forceinline__ void cp_wait() {
    asm volatile("cp.async.wait_group %0;\n" :: "n"(N) : "memory");
}

__device__ __forceinline__ float warp_sum(float v) {
    #pragma unroll
    for (int o = 16; o; o >>= 1) v += __shfl_xor_sync(0xffffffffu, v, o);
    return v;
}
__device__ __forceinline__ float warp_max(float v) {
    #pragma unroll
    for (int o = 16; o; o >>= 1) v = fmaxf(v, __shfl_xor_sync(0xffffffffu, v, o));
    return v;
}

// ---------------------------------------------------------------------------
// Kernel 0: pack weights fp32 -> fp16
// ---------------------------------------------------------------------------
__global__ void pack_w_kernel(const float* __restrict__ wq, const float* __restrict__ wk,
                              const float* __restrict__ wv, const float* __restrict__ wp) {
    const int NW = DIM * HID;  // 204800 (same count for wp)
    int i = blockIdx.x * blockDim.x + threadIdx.x;
    if (i < NW)               g_wq[i]          = __float2half_rn(wq[i]);
    else if (i < 2 * NW)      g_wk[i - NW]     = __float2half_rn(wk[i - NW]);
    else if (i < 3 * NW)      g_wv[i - 2 * NW] = __float2half_rn(wv[i - 2 * NW]);
    else if (i < 4 * NW)      g_wp[i - 3 * NW] = __float2half_rn(wp[i - 3 * NW]);
}

// ---------------------------------------------------------------------------
// Kernel 1: QKV projections.  C[65536,512] = A[65536,400] * W[400,512] + b
// Block tile 128x128, BK=32, 8 warps (4x2), warp tile 32x64.
// q output is pre-scaled by 1/sqrt(512).
// ---------------------------------------------------------------------------
__global__ __launch_bounds__(256) void qkv_kernel(
    const float* __restrict__ rgb, const float* __restrict__ pose,
    const float* __restrict__ bq, const float* __restrict__ bk,
    const float* __restrict__ bv) {
    const int z = blockIdx.z;
    const float*  A    = (z == 0) ? rgb : pose;
    const __half* W    = (z == 0) ? g_wq : (z == 1) ? g_wk : g_wv;
    const float*  bias = (z == 0) ? bq : (z == 1) ? bk : bv;
    __half*       dst  = (z == 0) ? g_q : (z == 1) ? g_k : g_v;
    const float   osc  = (z == 0) ? SOFTMAX_SCALE : 1.0f;

    const int m0 = blockIdx.x * 128, n0 = blockIdx.y * 128;
    __shared__ __half As[128][40];   // row-major [M][K], pad 8
    __shared__ __half Bs[32][136];   // [K][N] trans path, pad 8

    const int tid = threadIdx.x, lane = tid & 31, warp = tid >> 5;
    const int wm = warp & 3, wn = warp >> 2;        // warp tile 32 x 64
    const int br = tid >> 4, bc = (tid & 15) * 8;   // B loader: 16 rows/pass x 128 cols

    float acc[2][8][4];
    #pragma unroll
    for (int i = 0; i < 2; i++)
        #pragma unroll
        for (int j = 0; j < 8; j++)
            #pragma unroll
            for (int l = 0; l < 4; l++) acc[i][j][l] = 0.f;

    for (int k0 = 0; k0 < DIM; k0 += 32) {
        #pragma unroll
        for (int t = 0; t < 4; t++) {
            int i = tid + t * 256;
            int r = i >> 3, c4 = i & 7;
            int gk = k0 + c4 * 4;
            float4 val = make_float4(0.f, 0.f, 0.f, 0.f);
            if (gk < DIM) val = *(const float4*)(A + (size_t)(m0 + r) * DIM + gk);
            __half2* sp = (__half2*)&As[r][c4 * 4];
            sp[0] = __floats2half2_rn(val.x, val.y);
            sp[1] = __floats2half2_rn(val.z, val.w);
        }
        #pragma unroll
        for (int t = 0; t < 2; t++) {
            int r = br + t * 16;
            int gk = k0 + r;
            uint4 val = make_uint4(0, 0, 0, 0);
            if (gk < DIM) val = *(const uint4*)(W + (size_t)gk * HID + n0 + bc);
            *(uint4*)&Bs[r][bc] = val;
        }
        __syncthreads();

        #pragma unroll
        for (int ks = 0; ks < 32; ks += 16) {
            uint32_t af[2][4], bf[4][4];
            #pragma unroll
            for (int mt = 0; mt < 2; mt++)
                ldsm4(af[mt], cvta_s(&As[wm * 32 + mt * 16 + (lane & 15)][ks + (lane >> 4) * 8]));
            #pragma unroll
            for (int np = 0; np < 4; np++)
                ldsm4t(bf[np], cvta_s(&Bs[ks + (lane & 15)][wn * 64 + np * 16 + (lane >> 4) * 8]));
            #pragma unroll
            for (int mt = 0; mt < 2; mt++)
                #pragma unroll
                for (int nt = 0; nt < 8; nt++)
                    mma16816(acc[mt][nt], af[mt], &bf[nt >> 1][(nt & 1) * 2]);
        }
        __syncthreads();
    }

    const int row0 = m0 + wm * 32, col0 = n0 + wn * 64;
    #pragma unroll
    for (int mt = 0; mt < 2; mt++)
        #pragma unroll
        for (int nt = 0; nt < 8; nt++) {
            int r = row0 + mt * 16 + (lane >> 2);
            int c = col0 + nt * 8 + (lane & 3) * 2;
            float b0 = bias[c], b1 = bias[c + 1];
            *(__half2*)(dst + (size_t)r * HID + c) =
                __floats2half2_rn((acc[mt][nt][0] + b0) * osc, (acc[mt][nt][1] + b1) * osc);
            *(__half2*)(dst + (size_t)(r + 8) * HID + c) =
                __floats2half2_rn((acc[mt][nt][2] + b0) * osc, (acc[mt][nt][3] + b1) * osc);
        }
}

// ---------------------------------------------------------------------------
// Kernel 2: scores.  S[b] = Q[b]*K[b]^T (q pre-scaled).  M=N=2048, K=512.
// grid (16, 16, 32). Block 128x128, BK=32, 8 warps (4x2), warp tile 32x64.
// 2-stage cp.async double buffering. S stored fp16, streamed (evict-first).
// ---------------------------------------------------------------------------
__global__ __launch_bounds__(256) void scores_kernel() {
    const int b = blockIdx.z;
    const int m0 = blockIdx.x * 128, n0 = blockIdx.y * 128;
    const __half* Q = g_q + (size_t)b * SEQ * HID;
    const __half* K = g_k + (size_t)b * SEQ * HID;
    __half* S = g_s + (size_t)b * SEQ * SEQ;

    __shared__ __half As[2][128][40];  // [M][K]
    __shared__ __half Bs[2][128][40];  // [N][K]  (non-trans ldmatrix path)

    const int tid = threadIdx.x, lane = tid & 31, warp = tid >> 5;
    const int wm = warp & 3, wn = warp >> 2;  // warp tile 32 x 64
    const int lr = tid >> 2, lc = (tid & 3) * 8;  // loader coords: 64 rows/pass x 32 cols

    float acc[2][8][4];
    #pragma unroll
    for (int i = 0; i < 2; i++)
        #pragma unroll
        for (int j = 0; j < 8; j++)
            #pragma unroll
            for (int l = 0; l < 4; l++) acc[i][j][l] = 0.f;

    const int KT = HID / 32;  // 16 k-steps

    #pragma unroll
    for (int t = 0; t < 2; t++) {
        int r = lr + t * 64;
        cp16(cvta_s(&As[0][r][lc]), Q + (size_t)(m0 + r) * HID + lc);
        cp16(cvta_s(&Bs[0][r][lc]), K + (size_t)(n0 + r) * HID + lc);
    }
    cp_commit();

    for (int kt = 0; kt < KT; kt++) {
        const int buf = kt & 1;
        if (kt + 1 < KT) {
            const int k0 = (kt + 1) * 32;
            #pragma unroll
            for (int t = 0; t < 2; t++) {
                int r = lr + t * 64;
                cp16(cvta_s(&As[buf ^ 1][r][lc]), Q + (size_t)(m0 + r) * HID + k0 + lc);
                cp16(cvta_s(&Bs[buf ^ 1][r][lc]), K + (size_t)(n0 + r) * HID + k0 + lc);
            }
            cp_commit();
            cp_wait<1>();
        } else {
            cp_wait<0>();
        }
        __syncthreads();

        #pragma unroll
        for (int ks = 0; ks < 32; ks += 16) {
            uint32_t af[2][4], bf[4][4];
            #pragma unroll
            for (int mt = 0; mt < 2; mt++)
                ldsm4(af[mt], cvta_s(&As[buf][wm * 32 + mt * 16 + (lane & 15)][ks + (lane >> 4) * 8]));
            #pragma unroll
            for (int np = 0; np < 4; np++) {  // two n8 tiles per x4 (non-trans, rows=n)
                int n = wn * 64 + np * 16 + (lane & 7) + ((lane >> 4) << 3);
                int k = ks + ((lane >> 3) & 1) * 8;
                ldsm4(bf[np], cvta_s(&Bs[buf][n][k]));
            }
            #pragma unroll
            for (int mt = 0; mt < 2; mt++)
                #pragma unroll
                for (int nt = 0; nt < 8; nt++)
                    mma16816(acc[mt][nt], af[mt], &bf[nt >> 1][(nt & 1) * 2]);
        }
        __syncthreads();
    }

    const int row0 = m0 + wm * 32, col0 = n0 + wn * 64;
    #pragma unroll
    for (int mt = 0; mt < 2; mt++)
        #pragma unroll
        for (int nt = 0; nt < 8; nt++) {
            int r = row0 + mt * 16 + (lane >> 2);
            int c = col0 + nt * 8 + (lane & 3) * 2;
            __half2 h0 = __floats2half2_rn(acc[mt][nt][0], acc[mt][nt][1]);
            __half2 h1 = __floats2half2_rn(acc[mt][nt][2], acc[mt][nt][3]);
            __stcs((unsigned int*)(S + (size_t)r * SEQ + c), *(unsigned int*)&h0);
            __stcs((unsigned int*)(S + (size_t)(r + 8) * SEQ + c), *(unsigned int*)&h1);
        }
}

// ---------------------------------------------------------------------------
// Kernel 3: row softmax (one warp per row of 2048) over fp16 scores.
// Streaming loads/stores — S and P are single-use streams.
// ---------------------------------------------------------------------------
__global__ __launch_bounds__(256) void softmax_kernel() {
    const int row = blockIdx.x * 8 + (threadIdx.x >> 5);
    const int lane = threadIdx.x & 31;
    const float4* s = (const float4*)(g_s + (size_t)row * SEQ);  // 16B = 8 halves

    float v[64];
    float mx = -1e30f;
    #pragma unroll
    for (int i = 0; i < 8; i++) {
        float4 u = __ldcs(s + lane + i * 32);
        const __half2* hp = (const __half2*)&u;
        #pragma unroll
        for (int j = 0; j < 4; j++) {
            float2 f = __half22float2(hp[j]);
            v[8 * i + 2 * j + 0] = f.x;
            v[8 * i + 2 * j + 1] = f.y;
            mx = fmaxf(mx, fmaxf(f.x, f.y));
        }
    }
    mx = warp_max(mx);
    float sum = 0.f;
    #pragma unroll
    for (int i = 0; i < 64; i++) { v[i] = __expf(v[i] - mx); sum += v[i]; }
    sum = warp_sum(sum);
    const float inv = 1.0f / sum;

    float4* p = (float4*)(g_p + (size_t)row * SEQ);
    #pragma unroll
    for (int i = 0; i < 8; i++) {
        __half2 h[4];
        #pragma unroll
        for (int j = 0; j < 4; j++)
            h[j] = __floats2half2_rn(v[8 * i + 2 * j] * inv, v[8 * i + 2 * j + 1] * inv);
        __stcs(p + lane + i * 32, *(float4*)h);
    }
}

// ---------------------------------------------------------------------------
// Kernel 4: O[b] = P[b] * V[b].  M=2048, N=512, K=2048.
// grid (16, 4, 32). Block 128x128, BK=32, 8 warps (4x2), warp tile 32x64.
// 2-stage cp.async double buffering.
// ---------------------------------------------------------------------------
__global__ __launch_bounds__(256) void pv_kernel() {
    const int b = blockIdx.z;
    const int m0 = blockIdx.x * 128, n0 = blockIdx.y * 128;
    const __half* P = g_p + (size_t)b * SEQ * SEQ;
    const __half* V = g_v + (size_t)b * SEQ * HID;
    __half* O = g_o + (size_t)b * SEQ * HID;

    __shared__ __half As[2][128][40];   // [M][K]
    __shared__ __half Bs[2][32][136];   // [K][N] trans path, pad 8

    const int tid = threadIdx.x, lane = tid & 31, warp = tid >> 5;
    const int wm = warp & 3, wn = warp >> 2;           // warp tile 32 x 64
    const int lr = tid >> 2, lc = (tid & 3) * 8;        // A loader
    const int br = tid >> 4, bc = (tid & 15) * 8;       // B loader

    float acc[2][8][4];
    #pragma unroll
    for (int i = 0; i < 2; i++)
        #pragma unroll
        for (int j = 0; j < 8; j++)
            #pragma unroll
            for (int l = 0; l < 4; l++) acc[i][j][l] = 0.f;

    const int KT = SEQ / 32;  // 64 k-steps

    #pragma unroll
    for (int t = 0; t < 2; t++) {
        int r = lr + t * 64;
        cp16(cvta_s(&As[0][r][lc]), P + (size_t)(m0 + r) * SEQ + lc);
    }
    #pragma unroll
    for (int t = 0; t < 2; t++) {
        int r = br + t * 16;
        cp16(cvta_s(&Bs[0][r][bc]), V + (size_t)r * HID + n0 + bc);
    }
    cp_commit();

    for (int kt = 0; kt < KT; kt++) {
        const int buf = kt & 1;
        if (kt + 1 < KT) {
            const int k0 = (kt + 1) * 32;
            #pragma unroll
            for (int t = 0; t < 2; t++) {
                int r = lr + t * 64;
                cp16(cvta_s(&As[buf ^ 1][r][lc]), P + (size_t)(m0 + r) * SEQ + k0 + lc);
            }
            #pragma unroll
            for (int t = 0; t < 2; t++) {
                int r = br + t * 16;
                cp16(cvta_s(&Bs[buf ^ 1][r][bc]), V + (size_t)(k0 + r) * HID + n0 + bc);
            }
            cp_commit();
            cp_wait<1>();
        } else {
            cp_wait<0>();
        }
        __syncthreads();

        #pragma unroll
        for (int ks = 0; ks < 32; ks += 16) {
            uint32_t af[2][4], bf[4][4];
            #pragma unroll
            for (int mt = 0; mt < 2; mt++)
                ldsm4(af[mt], cvta_s(&As[buf][wm * 32 + mt * 16 + (lane & 15)][ks + (lane >> 4) * 8]));
            #pragma unroll
            for (int np = 0; np < 4; np++)
                ldsm4t(bf[np], cvta_s(&Bs[buf][ks + (lane & 15)][wn * 64 + np * 16 + (lane >> 4) * 8]));
            #pragma unroll
            for (int mt = 0; mt < 2; mt++)
                #pragma unroll
                for (int nt = 0; nt < 8; nt++)
                    mma16816(acc[mt][nt], af[mt], &bf[nt >> 1][(nt & 1) * 2]);
        }
        __syncthreads();
    }

    const int row0 = m0 + wm * 32, col0 = n0 + wn * 64;
    #pragma unroll
    for (int mt = 0; mt < 2; mt++)
        #pragma unroll
        for (int nt = 0; nt < 8; nt++) {
            int r = row0 + mt * 16 + (lane >> 2);
            int c = col0 + nt * 8 + (lane & 3) * 2;
            *(__half2*)(O + (size_t)r * HID + c) =
                __floats2half2_rn(acc[mt][nt][0], acc[mt][nt][1]);
            *(__half2*)(O + (size_t)(r + 8) * HID + c) =
                __floats2half2_rn(acc[mt][nt][2], acc[mt][nt][3]);
        }
}

// ---------------------------------------------------------------------------
// Kernel 5: proj = O * Wp + bp.  M=65536, N=400, K=512.
// grid (512, 4). Block 128x128. Output streamed. Guard N < 400.
// ---------------------------------------------------------------------------
__global__ __launch_bounds__(256) void proj_kernel(const float* __restrict__ bp) {
    const int m0 = blockIdx.x * 128, n0 = blockIdx.y * 128;

    __shared__ __half As[128][40];
    __shared__ __half Bs[32][136];

    const int tid = threadIdx.x, lane = tid & 31, warp = tid >> 5;
    const int wm = warp & 3, wn = warp >> 2;
    const int br = tid >> 4, bc = (tid & 15) * 8;

    float acc[2][8][4];
    #pragma unroll
    for (int i = 0; i < 2; i++)
        #pragma unroll
        for (int j = 0; j < 8; j++)
            #pragma unroll
            for (int l = 0; l < 4; l++) acc[i][j][l] = 0.f;

    for (int k0 = 0; k0 < HID; k0 += 32) {
        #pragma unroll
        for (int t = 0; t < 2; t++) {
            int i = tid + t * 256;
            int r = i >> 2, c = (i & 3) * 8;
            *(uint4*)&As[r][c] = *(const uint4*)(g_o + (size_t)(m0 + r) * HID + k0 + c);
        }
        #pragma unroll
        for (int t = 0; t < 2; t++) {
            int r = br + t * 16;
            int n = n0 + bc;
            uint4 val = make_uint4(0, 0, 0, 0);
            if (n < DIM) val = *(const uint4*)(g_wp + (size_t)(k0 + r) * DIM + n);
            *(uint4*)&Bs[r][bc] = val;
        }
        __syncthreads();

        #pragma unroll
        for (int ks = 0; ks < 32; ks += 16) {
            uint32_t af[2][4], bf[4][4];
            #pragma unroll
            for (int mt = 0; mt < 2; mt++)
                ldsm4(af[mt], cvta_s(&As[wm * 32 + mt * 16 + (lane & 15)][ks + (lane >> 4) * 8]));
            #pragma unroll
            for (int np = 0; np < 4; np++)
                ldsm4t(bf[np], cvta_s(&Bs[ks + (lane & 15)][wn * 64 + np * 16 + (lane >> 4) * 8]));
            #pragma unroll
            for (int mt = 0; mt < 2; mt++)
                #pragma unroll
                for (int nt = 0; nt < 8; nt++)
                    mma16816(acc[mt][nt], af[mt], &bf[nt >> 1][(nt & 1) * 2]);
        }
        __syncthreads();
    }

    const int row0 = m0 + wm * 32, col0 = n0 + wn * 64;
    #pragma unroll
    for (int mt = 0; mt < 2; mt++)
        #pragma unroll
        for (int nt = 0; nt < 8; nt++) {
            int c = col0 + nt * 8 + (lane & 3) * 2;
            if (c < DIM) {
                int r = row0 + mt * 16 + (lane >> 2);
                float b0 = bp[c], b1 = bp[c + 1];
                __stcs((float2*)(g_proj + (size_t)r * DIM + c),
                       make_float2(acc[mt][nt][0] + b0, acc[mt][nt][1] + b1));
                __stcs((float2*)(g_proj + (size_t)(r + 8) * DIM + c),
                       make_float2(acc[mt][nt][2] + b0, acc[mt][nt][3] + b1));
            }
        }
}

// ---------------------------------------------------------------------------
// Kernel 6: gated residual + LayerNorm over 400.  One warp per row.
// ---------------------------------------------------------------------------
__global__ __launch_bounds__(256) void ln_kernel(
    const float* __restrict__ rgb, const float* __restrict__ gamma,
    const float* __restrict__ beta, const float* __restrict__ gate,
    float* __restrict__ out) {
    const int row = blockIdx.x * 8 + (threadIdx.x >> 5);
    const int lane = threadIdx.x & 31;
    const float gt = gate[0];

    const float4* pr = (const float4*)(g_proj + (size_t)row * DIM);
    const float4* rg = (const float4*)(rgb + (size_t)row * DIM);

    float x[16];
    float sum = 0.f;
    #pragma unroll
    for (int i = 0; i < 4; i++) {
        int idx = lane + i * 32;
        if (idx < 100) {
            float4 p4 = __ldcs(pr + idx);
            float4 r4 = rg[idx];
            x[4 * i + 0] = r4.x + gt * p4.x;
            x[4 * i + 1] = r4.y + gt * p4.y;
            x[4 * i + 2] = r4.z + gt * p4.z;
            x[4 * i + 3] = r4.w + gt * p4.w;
            sum += x[4 * i] + x[4 * i + 1] + x[4 * i + 2] + x[4 * i + 3];
        } else {
            x[4 * i] = x[4 * i + 1] = x[4 * i + 2] = x[4 * i + 3] = 0.f;
        }
    }
    const float mean = warp_sum(sum) * (1.0f / DIM);

    float vs = 0.f;
    #pragma unroll
    for (int i = 0; i < 4; i++) {
        int idx = lane + i * 32;
        if (idx < 100) {
            #pragma unroll
            for (int j = 0; j < 4; j++) {
                float d = x[4 * i + j] - mean;
                vs += d * d;
            }
        }
    }
    const float rstd = rsqrtf(warp_sum(vs) * (1.0f / DIM) + LN_EPS);

    float4* o4 = (float4*)(out + (size_t)row * DIM);
    const float4* g4 = (const float4*)gamma;
    const float4* b4 = (const float4*)beta;
    #pragma unroll
    for (int i = 0; i < 4; i++) {
        int idx = lane + i * 32;
        if (idx < 100) {
            float4 gm = g4[idx], bt = b4[idx];
            float4 r;
            r.x = (x[4 * i + 0] - mean) * rstd * gm.x + bt.x;
            r.y = (x[4 * i + 1] - mean) * rstd * gm.y + bt.y;
            r.z = (x[4 * i + 2] - mean) * rstd * gm.z + bt.z;
            r.w = (x[4 * i + 3] - mean) * rstd * gm.w + bt.w;
            o4[idx] = r;
        }
    }
}

// ---------------------------------------------------------------------------
// Launch
// ---------------------------------------------------------------------------
extern "C" void kernel_launch(void* const* d_in, const int* in_sizes, int n_in,
                              void* d_out, int out_size) {
    (void)in_sizes; (void)n_in; (void)out_size;
    const float* rgb   = (const float*)d_in[0];
    const float* pose  = (const float*)d_in[1];
    const float* Wq    = (const float*)d_in[2];
    const float* bq    = (const float*)d_in[3];
    const float* Wk    = (const float*)d_in[4];
    const float* bk    = (const float*)d_in[5];
    const float* Wv    = (const float*)d_in[6];
    const float* bv    = (const float*)d_in[7];
    const float* Wp    = (const float*)d_in[8];
    const float* bp    = (const float*)d_in[9];
    const float* gamma = (const float*)d_in[10];
    const float* beta  = (const float*)d_in[11];
    const float* gate  = (const float*)d_in[12];
    float* out = (float*)d_out;

    pack_w_kernel<<<(4 * DIM * HID + 255) / 256, 256>>>(Wq, Wk, Wv, Wp);
    qkv_kernel<<<dim3(MROWS / 128, HID / 128, 3), 256>>>(rgb, pose, bq, bk, bv);
    scores_kernel<<<dim3(SEQ / 128, SEQ / 128, NB), 256>>>();
    softmax_kernel<<<MROWS / 8, 256>>>();
    pv_kernel<<<dim3(SEQ / 128, HID / 128, NB), 256>>>();
    proj_kernel<<<dim3(MROWS / 128, (DIM + 127) / 128, 1), 256>>>(bp);
    ln_kernel<<<MROWS / 8, 256>>>(rgb, gamma, beta, gate, out);
}

// round 14
// speedup vs baseline: 1.0676x; 1.0411x over previous
#include <cuda_runtime.h>
#include <cuda_fp16.h>
#include <cstdint>

// Problem dims (fixed)
#define NB   32
#define SEQ  2048
#define DIM  400
#define DIMP 416                  // DIM padded to 13*32 for guard-free K loop
#define HID  512
#define MROWS (NB * SEQ)          // 65536
#define LN_EPS 1e-5f
#define SOFTMAX_SCALE 0.04419417382415922f  // 1/sqrt(512)

// ---------------------------------------------------------------------------
// Scratch (device globals — allocation-free per harness rules)
// ---------------------------------------------------------------------------
__device__ __half g_rgb[(size_t)MROWS * DIMP];       // 54.5 MB fp16 (padded)
__device__ __half g_pose[(size_t)MROWS * DIMP];      // 54.5 MB fp16 (padded)
__device__ __half g_q[(size_t)MROWS * HID];          // 64 MB (pre-scaled by 1/sqrt(512))
__device__ __half g_k[(size_t)MROWS * HID];          // 64 MB
__device__ __half g_v[(size_t)MROWS * HID];          // 64 MB
__device__ __half g_o[(size_t)MROWS * HID];          // 64 MB
__device__ __half g_s[(size_t)NB * SEQ * SEQ];       // 256 MB  scores fp16 (single-use stream)
__device__ __half g_p[(size_t)NB * SEQ * SEQ];       // 256 MB  probs fp16  (single-use stream)
__device__ float  g_proj[(size_t)MROWS * DIM];       // 104 MB  (single-use stream)
__device__ __half g_wq[DIMP * HID];                  // zero-padded rows 400..415
__device__ __half g_wk[DIMP * HID];
__device__ __half g_wv[DIMP * HID];
__device__ __half g_wp[HID * DIM];

// ---------------------------------------------------------------------------
// MMA / ldmatrix / cp.async helpers
// ---------------------------------------------------------------------------
__device__ __forceinline__ uint32_t cvta_s(const void* p) {
    return (uint32_t)__cvta_generic_to_shared(p);
}

__device__ __forceinline__ void ldsm4(uint32_t* r, uint32_t a) {
    asm volatile("ldmatrix.sync.aligned.m8n8.x4.shared.b16 {%0,%1,%2,%3}, [%4];\n"
                 : "=r"(r[0]), "=r"(r[1]), "=r"(r[2]), "=r"(r[3]) : "r"(a));
}
__device__ __forceinline__ void ldsm4t(uint32_t* r, uint32_t a) {
    asm volatile("ldmatrix.sync.aligned.m8n8.x4.trans.shared.b16 {%0,%1,%2,%3}, [%4];\n"
                 : "=r"(r[0]), "=r"(r[1]), "=r"(r[2]), "=r"(r[3]) : "r"(a));
}
__device__ __forceinline__ void mma16816(float* c, const uint32_t* a, const uint32_t* b) {
    asm volatile(
        "mma.sync.aligned.m16n8k16.row.col.f32.f16.f16.f32 "
        "{%0,%1,%2,%3}, {%4,%5,%6,%7}, {%8,%9}, {%0,%1,%2,%3};\n"
        : "+f"(c[0]), "+f"(c[1]), "+f"(c[2]), "+f"(c[3])
        : "r"(a[0]), "r"(a[1]), "r"(a[2]), "r"(a[3]), "r"(b[0]), "r"(b[1]));
}

__device__ __forceinline__ void cp16(uint32_t dst, const void* src) {
    asm volatile("cp.async.cg.shared.global [%0], [%1], 16;\n" :: "r"(dst), "l"(src));
}
__device__ __forceinline__ void cp_commit() {
    asm volatile("cp.async.commit_group;\n" ::: "memory");
}
template <int N>
__device__ __forceinline__ void cp_wait() {
    asm volatile("cp.async.wait_group %0;\n" :: "n"(N) : "memory");
}

__device__ __forceinline__ float warp_sum(float v) {
    #pragma unroll
    for (int o = 16; o; o >>= 1) v += __shfl_xor_sync(0xffffffffu, v, o);
    return v;
}
__device__ __forceinline__ float warp_max(float v) {
    #pragma unroll
    for (int o = 16; o; o >>= 1) v = fmaxf(v, __shfl_xor_sync(0xffffffffu, v, o));
    return v;
}

// ---------------------------------------------------------------------------
// Kernel 0a: pack activations fp32 -> fp16, pad cols 400..415 with zeros.
// grid.y: 0 = rgb, 1 = pose. Each thread writes one half2.
// ---------------------------------------------------------------------------
__global__ __launch_bounds__(256) void pack_in_kernel(
    const float* __restrict__ rgb, const float* __restrict__ pose) {
    const size_t i = (size_t)blockIdx.x * blockDim.x + threadIdx.x;
    const size_t total = (size_t)MROWS * (DIMP / 2);
    if (i >= total) return;
    const int row = (int)(i / (DIMP / 2));
    const int c = (int)(i % (DIMP / 2)) * 2;
    const float* src = blockIdx.y ? pose : rgb;
    __half* dst = blockIdx.y ? g_pose : g_rgb;
    __half2 h = __floats2half2_rn(0.f, 0.f);
    if (c < DIM) {
        const float* s = src + (size_t)row * DIM + c;
        h = __floats2half2_rn(s[0], s[1]);
    }
    *(__half2*)(dst + (size_t)row * DIMP + c) = h;
}

// ---------------------------------------------------------------------------
// Kernel 0b: pack weights fp32 -> fp16 (wq/wk/wv zero-padded to 416 rows)
// ---------------------------------------------------------------------------
__global__ __launch_bounds__(256) void pack_w_kernel(
    const float* __restrict__ wq, const float* __restrict__ wk,
    const float* __restrict__ wv, const float* __restrict__ wp) {
    const int NWP = DIMP * HID;  // 212992
    const int NW  = HID * DIM;   // 204800
    int i = blockIdx.x * blockDim.x + threadIdx.x;
    if (i < 3 * NWP) {
        int w = i / NWP, j = i % NWP;
        int r = j / HID, c = j % HID;
        const float* src = (w == 0) ? wq : (w == 1) ? wk : wv;
        __half* dst = (w == 0) ? g_wq : (w == 1) ? g_wk : g_wv;
        dst[j] = __float2half_rn(r < DIM ? src[r * HID + c] : 0.f);
    } else if (i < 3 * NWP + NW) {
        int j = i - 3 * NWP;
        g_wp[j] = __float2half_rn(wp[j]);
    }
}

// ---------------------------------------------------------------------------
// Kernel 1: QKV projections.  C[65536,512] = A[65536,416p] * W[416p,512] + b
// Block tile 128x128, BK=32 x 13 guard-free tiles, 8 warps, warp tile 32x64.
// 2-stage cp.async double buffering. q output pre-scaled by 1/sqrt(512).
// ---------------------------------------------------------------------------
__global__ __launch_bounds__(256) void qkv_kernel(
    const float* __restrict__ bq, const float* __restrict__ bk,
    const float* __restrict__ bv) {
    const int z = blockIdx.z;
    const __half* A    = (z == 0) ? g_rgb : g_pose;
    const __half* W    = (z == 0) ? g_wq : (z == 1) ? g_wk : g_wv;
    const float*  bias = (z == 0) ? bq : (z == 1) ? bk : bv;
    __half*       dst  = (z == 0) ? g_q : (z == 1) ? g_k : g_v;
    const float   osc  = (z == 0) ? SOFTMAX_SCALE : 1.0f;

    const int m0 = blockIdx.x * 128, n0 = blockIdx.y * 128;
    __shared__ __half As[2][128][40];   // [M][K], pad 8
    __shared__ __half Bs[2][32][136];   // [K][N] trans path, pad 8

    const int tid = threadIdx.x, lane = tid & 31, warp = tid >> 5;
    const int wm = warp & 3, wn = warp >> 2;        // warp tile 32 x 64
    const int lr = tid >> 2, lc = (tid & 3) * 8;    // A loader: 64 rows/pass x 32 cols
    const int br = tid >> 4, bc = (tid & 15) * 8;   // B loader: 16 rows/pass x 128 cols

    float acc[2][8][4];
    #pragma unroll
    for (int i = 0; i < 2; i++)
        #pragma unroll
        for (int j = 0; j < 8; j++)
            #pragma unroll
            for (int l = 0; l < 4; l++) acc[i][j][l] = 0.f;

    const int KT = DIMP / 32;  // 13 k-steps

    #pragma unroll
    for (int t = 0; t < 2; t++) {
        int r = lr + t * 64;
        cp16(cvta_s(&As[0][r][lc]), A + (size_t)(m0 + r) * DIMP + lc);
    }
    #pragma unroll
    for (int t = 0; t < 2; t++) {
        int r = br + t * 16;
        cp16(cvta_s(&Bs[0][r][bc]), W + (size_t)r * HID + n0 + bc);
    }
    cp_commit();

    for (int kt = 0; kt < KT; kt++) {
        const int buf = kt & 1;
        if (kt + 1 < KT) {
            const int k0 = (kt + 1) * 32;
            #pragma unroll
            for (int t = 0; t < 2; t++) {
                int r = lr + t * 64;
                cp16(cvta_s(&As[buf ^ 1][r][lc]), A + (size_t)(m0 + r) * DIMP + k0 + lc);
            }
            #pragma unroll
            for (int t = 0; t < 2; t++) {
                int r = br + t * 16;
                cp16(cvta_s(&Bs[buf ^ 1][r][bc]), W + (size_t)(k0 + r) * HID + n0 + bc);
            }
            cp_commit();
            cp_wait<1>();
        } else {
            cp_wait<0>();
        }
        __syncthreads();

        #pragma unroll
        for (int ks = 0; ks < 32; ks += 16) {
            uint32_t af[2][4], bf[4][4];
            #pragma unroll
            for (int mt = 0; mt < 2; mt++)
                ldsm4(af[mt], cvta_s(&As[buf][wm * 32 + mt * 16 + (lane & 15)][ks + (lane >> 4) * 8]));
            #pragma unroll
            for (int np = 0; np < 4; np++)
                ldsm4t(bf[np], cvta_s(&Bs[buf][ks + (lane & 15)][wn * 64 + np * 16 + (lane >> 4) * 8]));
            #pragma unroll
            for (int mt = 0; mt < 2; mt++)
                #pragma unroll
                for (int nt = 0; nt < 8; nt++)
                    mma16816(acc[mt][nt], af[mt], &bf[nt >> 1][(nt & 1) * 2]);
        }
        __syncthreads();
    }

    const int row0 = m0 + wm * 32, col0 = n0 + wn * 64;
    #pragma unroll
    for (int mt = 0; mt < 2; mt++)
        #pragma unroll
        for (int nt = 0; nt < 8; nt++) {
            int r = row0 + mt * 16 + (lane >> 2);
            int c = col0 + nt * 8 + (lane & 3) * 2;
            float b0 = bias[c], b1 = bias[c + 1];
            *(__half2*)(dst + (size_t)r * HID + c) =
                __floats2half2_rn((acc[mt][nt][0] + b0) * osc, (acc[mt][nt][1] + b1) * osc);
            *(__half2*)(dst + (size_t)(r + 8) * HID + c) =
                __floats2half2_rn((acc[mt][nt][2] + b0) * osc, (acc[mt][nt][3] + b1) * osc);
        }
}

// ---------------------------------------------------------------------------
// Kernel 2: scores.  S[b] = Q[b]*K[b]^T (q pre-scaled).  M=N=2048, K=512.
// grid (16, 16, 32). Block 128x128, BK=32, 8 warps (4x2), warp tile 32x64.
// 2-stage cp.async double buffering. S stored fp16, streamed (evict-first).
// ---------------------------------------------------------------------------
__global__ __launch_bounds__(256) void scores_kernel() {
    const int b = blockIdx.z;
    const int m0 = blockIdx.x * 128, n0 = blockIdx.y * 128;
    const __half* Q = g_q + (size_t)b * SEQ * HID;
    const __half* K = g_k + (size_t)b * SEQ * HID;
    __half* S = g_s + (size_t)b * SEQ * SEQ;

    __shared__ __half As[2][128][40];  // [M][K]
    __shared__ __half Bs[2][128][40];  // [N][K]  (non-trans ldmatrix path)

    const int tid = threadIdx.x, lane = tid & 31, warp = tid >> 5;
    const int wm = warp & 3, wn = warp >> 2;  // warp tile 32 x 64
    const int lr = tid >> 2, lc = (tid & 3) * 8;  // loader coords: 64 rows/pass x 32 cols

    float acc[2][8][4];
    #pragma unroll
    for (int i = 0; i < 2; i++)
        #pragma unroll
        for (int j = 0; j < 8; j++)
            #pragma unroll
            for (int l = 0; l < 4; l++) acc[i][j][l] = 0.f;

    const int KT = HID / 32;  // 16 k-steps

    #pragma unroll
    for (int t = 0; t < 2; t++) {
        int r = lr + t * 64;
        cp16(cvta_s(&As[0][r][lc]), Q + (size_t)(m0 + r) * HID + lc);
        cp16(cvta_s(&Bs[0][r][lc]), K + (size_t)(n0 + r) * HID + lc);
    }
    cp_commit();

    for (int kt = 0; kt < KT; kt++) {
        const int buf = kt & 1;
        if (kt + 1 < KT) {
            const int k0 = (kt + 1) * 32;
            #pragma unroll
            for (int t = 0; t < 2; t++) {
                int r = lr + t * 64;
                cp16(cvta_s(&As[buf ^ 1][r][lc]), Q + (size_t)(m0 + r) * HID + k0 + lc);
                cp16(cvta_s(&Bs[buf ^ 1][r][lc]), K + (size_t)(n0 + r) * HID + k0 + lc);
            }
            cp_commit();
            cp_wait<1>();
        } else {
            cp_wait<0>();
        }
        __syncthreads();

        #pragma unroll
        for (int ks = 0; ks < 32; ks += 16) {
            uint32_t af[2][4], bf[4][4];
            #pragma unroll
            for (int mt = 0; mt < 2; mt++)
                ldsm4(af[mt], cvta_s(&As[buf][wm * 32 + mt * 16 + (lane & 15)][ks + (lane >> 4) * 8]));
            #pragma unroll
            for (int np = 0; np < 4; np++) {  // two n8 tiles per x4 (non-trans, rows=n)
                int n = wn * 64 + np * 16 + (lane & 7) + ((lane >> 4) << 3);
                int k = ks + ((lane >> 3) & 1) * 8;
                ldsm4(bf[np], cvta_s(&Bs[buf][n][k]));
            }
            #pragma unroll
            for (int mt = 0; mt < 2; mt++)
                #pragma unroll
                for (int nt = 0; nt < 8; nt++)
                    mma16816(acc[mt][nt], af[mt], &bf[nt >> 1][(nt & 1) * 2]);
        }
        __syncthreads();
    }

    const int row0 = m0 + wm * 32, col0 = n0 + wn * 64;
    #pragma unroll
    for (int mt = 0; mt < 2; mt++)
        #pragma unroll
        for (int nt = 0; nt < 8; nt++) {
            int r = row0 + mt * 16 + (lane >> 2);
            int c = col0 + nt * 8 + (lane & 3) * 2;
            __half2 h0 = __floats2half2_rn(acc[mt][nt][0], acc[mt][nt][1]);
            __half2 h1 = __floats2half2_rn(acc[mt][nt][2], acc[mt][nt][3]);
            __stcs((unsigned int*)(S + (size_t)r * SEQ + c), *(unsigned int*)&h0);
            __stcs((unsigned int*)(S + (size_t)(r + 8) * SEQ + c), *(unsigned int*)&h1);
        }
}

// ---------------------------------------------------------------------------
// Kernel 3: row softmax (one warp per row of 2048) over fp16 scores.
// Streaming loads/stores — S and P are single-use streams.
// ---------------------------------------------------------------------------
__global__ __launch_bounds__(256) void softmax_kernel() {
    const int row = blockIdx.x * 8 + (threadIdx.x >> 5);
    const int lane = threadIdx.x & 31;
    const float4* s = (const float4*)(g_s + (size_t)row * SEQ);  // 16B = 8 halves

    float v[64];
    float mx = -1e30f;
    #pragma unroll
    for (int i = 0; i < 8; i++) {
        float4 u = __ldcs(s + lane + i * 32);
        const __half2* hp = (const __half2*)&u;
        #pragma unroll
        for (int j = 0; j < 4; j++) {
            float2 f = __half22float2(hp[j]);
            v[8 * i + 2 * j + 0] = f.x;
            v[8 * i + 2 * j + 1] = f.y;
            mx = fmaxf(mx, fmaxf(f.x, f.y));
        }
    }
    mx = warp_max(mx);
    float sum = 0.f;
    #pragma unroll
    for (int i = 0; i < 64; i++) { v[i] = __expf(v[i] - mx); sum += v[i]; }
    sum = warp_sum(sum);
    const float inv = 1.0f / sum;

    float4* p = (float4*)(g_p + (size_t)row * SEQ);
    #pragma unroll
    for (int i = 0; i < 8; i++) {
        __half2 h[4];
        #pragma unroll
        for (int j = 0; j < 4; j++)
            h[j] = __floats2half2_rn(v[8 * i + 2 * j] * inv, v[8 * i + 2 * j + 1] * inv);
        __stcs(p + lane + i * 32, *(float4*)h);
    }
}

// ---------------------------------------------------------------------------
// Kernel 4: O[b] = P[b] * V[b].  M=2048, N=512, K=2048.
// grid (16, 4, 32). Block 128x128, BK=32, 8 warps (4x2), warp tile 32x64.
// 2-stage cp.async double buffering.
// ---------------------------------------------------------------------------
__global__ __launch_bounds__(256) void pv_kernel() {
    const int b = blockIdx.z;
    const int m0 = blockIdx.x * 128, n0 = blockIdx.y * 128;
    const __half* P = g_p + (size_t)b * SEQ * SEQ;
    const __half* V = g_v + (size_t)b * SEQ * HID;
    __half* O = g_o + (size_t)b * SEQ * HID;

    __shared__ __half As[2][128][40];   // [M][K]
    __shared__ __half Bs[2][32][136];   // [K][N] trans path, pad 8

    const int tid = threadIdx.x, lane = tid & 31, warp = tid >> 5;
    const int wm = warp & 3, wn = warp >> 2;           // warp tile 32 x 64
    const int lr = tid >> 2, lc = (tid & 3) * 8;        // A loader
    const int br = tid >> 4, bc = (tid & 15) * 8;       // B loader

    float acc[2][8][4];
    #pragma unroll
    for (int i = 0; i < 2; i++)
        #pragma unroll
        for (int j = 0; j < 8; j++)
            #pragma unroll
            for (int l = 0; l < 4; l++) acc[i][j][l] = 0.f;

    const int KT = SEQ / 32;  // 64 k-steps

    #pragma unroll
    for (int t = 0; t < 2; t++) {
        int r = lr + t * 64;
        cp16(cvta_s(&As[0][r][lc]), P + (size_t)(m0 + r) * SEQ + lc);
    }
    #pragma unroll
    for (int t = 0; t < 2; t++) {
        int r = br + t * 16;
        cp16(cvta_s(&Bs[0][r][bc]), V + (size_t)r * HID + n0 + bc);
    }
    cp_commit();

    for (int kt = 0; kt < KT; kt++) {
        const int buf = kt & 1;
        if (kt + 1 < KT) {
            const int k0 = (kt + 1) * 32;
            #pragma unroll
            for (int t = 0; t < 2; t++) {
                int r = lr + t * 64;
                cp16(cvta_s(&As[buf ^ 1][r][lc]), P + (size_t)(m0 + r) * SEQ + k0 + lc);
            }
            #pragma unroll
            for (int t = 0; t < 2; t++) {
                int r = br + t * 16;
                cp16(cvta_s(&Bs[buf ^ 1][r][bc]), V + (size_t)(k0 + r) * HID + n0 + bc);
            }
            cp_commit();
            cp_wait<1>();
        } else {
            cp_wait<0>();
        }
        __syncthreads();

        #pragma unroll
        for (int ks = 0; ks < 32; ks += 16) {
            uint32_t af[2][4], bf[4][4];
            #pragma unroll
            for (int mt = 0; mt < 2; mt++)
                ldsm4(af[mt], cvta_s(&As[buf][wm * 32 + mt * 16 + (lane & 15)][ks + (lane >> 4) * 8]));
            #pragma unroll
            for (int np = 0; np < 4; np++)
                ldsm4t(bf[np], cvta_s(&Bs[buf][ks + (lane & 15)][wn * 64 + np * 16 + (lane >> 4) * 8]));
            #pragma unroll
            for (int mt = 0; mt < 2; mt++)
                #pragma unroll
                for (int nt = 0; nt < 8; nt++)
                    mma16816(acc[mt][nt], af[mt], &bf[nt >> 1][(nt & 1) * 2]);
        }
        __syncthreads();
    }

    const int row0 = m0 + wm * 32, col0 = n0 + wn * 64;
    #pragma unroll
    for (int mt = 0; mt < 2; mt++)
        #pragma unroll
        for (int nt = 0; nt < 8; nt++) {
            int r = row0 + mt * 16 + (lane >> 2);
            int c = col0 + nt * 8 + (lane & 3) * 2;
            *(__half2*)(O + (size_t)r * HID + c) =
                __floats2half2_rn(acc[mt][nt][0], acc[mt][nt][1]);
            *(__half2*)(O + (size_t)(r + 8) * HID + c) =
                __floats2half2_rn(acc[mt][nt][2], acc[mt][nt][3]);
        }
}

// ---------------------------------------------------------------------------
// Kernel 5: proj = O * Wp + bp.  M=65536, N=400, K=512.
// grid (512, 4). Block 128x128. Output streamed. Guard N < 400.
// ---------------------------------------------------------------------------
__global__ __launch_bounds__(256) void proj_kernel(const float* __restrict__ bp) {
    const int m0 = blockIdx.x * 128, n0 = blockIdx.y * 128;

    __shared__ __half As[128][40];
    __shared__ __half Bs[32][136];

    const int tid = threadIdx.x, lane = tid & 31, warp = tid >> 5;
    const int wm = warp & 3, wn = warp >> 2;
    const int br = tid >> 4, bc = (tid & 15) * 8;

    float acc[2][8][4];
    #pragma unroll
    for (int i = 0; i < 2; i++)
        #pragma unroll
        for (int j = 0; j < 8; j++)
            #pragma unroll
            for (int l = 0; l < 4; l++) acc[i][j][l] = 0.f;

    for (int k0 = 0; k0 < HID; k0 += 32) {
        #pragma unroll
        for (int t = 0; t < 2; t++) {
            int i = tid + t * 256;
            int r = i >> 2, c = (i & 3) * 8;
            *(uint4*)&As[r][c] = *(const uint4*)(g_o + (size_t)(m0 + r) * HID + k0 + c);
        }
        #pragma unroll
        for (int t = 0; t < 2; t++) {
            int r = br + t * 16;
            int n = n0 + bc;
            uint4 val = make_uint4(0, 0, 0, 0);
            if (n < DIM) val = *(const uint4*)(g_wp + (size_t)(k0 + r) * DIM + n);
            *(uint4*)&Bs[r][bc] = val;
        }
        __syncthreads();

        #pragma unroll
        for (int ks = 0; ks < 32; ks += 16) {
            uint32_t af[2][4], bf[4][4];
            #pragma unroll
            for (int mt = 0; mt < 2; mt++)
                ldsm4(af[mt], cvta_s(&As[wm * 32 + mt * 16 + (lane & 15)][ks + (lane >> 4) * 8]));
            #pragma unroll
            for (int np = 0; np < 4; np++)
                ldsm4t(bf[np], cvta_s(&Bs[ks + (lane & 15)][wn * 64 + np * 16 + (lane >> 4) * 8]));
            #pragma unroll
            for (int mt = 0; mt < 2; mt++)
                #pragma unroll
                for (int nt = 0; nt < 8; nt++)
                    mma16816(acc[mt][nt], af[mt], &bf[nt >> 1][(nt & 1) * 2]);
        }
        __syncthreads();
    }

    const int row0 = m0 + wm * 32, col0 = n0 + wn * 64;
    #pragma unroll
    for (int mt = 0; mt < 2; mt++)
        #pragma unroll
        for (int nt = 0; nt < 8; nt++) {
            int c = col0 + nt * 8 + (lane & 3) * 2;
            if (c < DIM) {
                int r = row0 + mt * 16 + (lane >> 2);
                float b0 = bp[c], b1 = bp[c + 1];
                __stcs((float2*)(g_proj + (size_t)r * DIM + c),
                       make_float2(acc[mt][nt][0] + b0, acc[mt][nt][1] + b1));
                __stcs((float2*)(g_proj + (size_t)(r + 8) * DIM + c),
                       make_float2(acc[mt][nt][2] + b0, acc[mt][nt][3] + b1));
            }
        }
}

// ---------------------------------------------------------------------------
// Kernel 6: gated residual + LayerNorm over 400.  One warp per row.
// ---------------------------------------------------------------------------
__global__ __launch_bounds__(256) void ln_kernel(
    const float* __restrict__ rgb, const float* __restrict__ gamma,
    const float* __restrict__ beta, const float* __restrict__ gate,
    float* __restrict__ out) {
    const int row = blockIdx.x * 8 + (threadIdx.x >> 5);
    const int lane = threadIdx.x & 31;
    const float gt = gate[0];

    const float4* pr = (const float4*)(g_proj + (size_t)row * DIM);
    const float4* rg = (const float4*)(rgb + (size_t)row * DIM);

    float x[16];
    float sum = 0.f;
    #pragma unroll
    for (int i = 0; i < 4; i++) {
        int idx = lane + i * 32;
        if (idx < 100) {
            float4 p4 = __ldcs(pr + idx);
            float4 r4 = rg[idx];
            x[4 * i + 0] = r4.x + gt * p4.x;
            x[4 * i + 1] = r4.y + gt * p4.y;
            x[4 * i + 2] = r4.z + gt * p4.z;
            x[4 * i + 3] = r4.w + gt * p4.w;
            sum += x[4 * i] + x[4 * i + 1] + x[4 * i + 2] + x[4 * i + 3];
        } else {
            x[4 * i] = x[4 * i + 1] = x[4 * i + 2] = x[4 * i + 3] = 0.f;
        }
    }
    const float mean = warp_sum(sum) * (1.0f / DIM);

    float vs = 0.f;
    #pragma unroll
    for (int i = 0; i < 4; i++) {
        int idx = lane + i * 32;
        if (idx < 100) {
            #pragma unroll
            for (int j = 0; j < 4; j++) {
                float d = x[4 * i + j] - mean;
                vs += d * d;
            }
        }
    }
    const float rstd = rsqrtf(warp_sum(vs) * (1.0f / DIM) + LN_EPS);

    float4* o4 = (float4*)(out + (size_t)row * DIM);
    const float4* g4 = (const float4*)gamma;
    const float4* b4 = (const float4*)beta;
    #pragma unroll
    for (int i = 0; i < 4; i++) {
        int idx = lane + i * 32;
        if (idx < 100) {
            float4 gm = g4[idx], bt = b4[idx];
            float4 r;
            r.x = (x[4 * i + 0] - mean) * rstd * gm.x + bt.x;
            r.y = (x[4 * i + 1] - mean) * rstd * gm.y + bt.y;
            r.z = (x[4 * i + 2] - mean) * rstd * gm.z + bt.z;
            r.w = (x[4 * i + 3] - mean) * rstd * gm.w + bt.w;
            o4[idx] = r;
        }
    }
}

// ---------------------------------------------------------------------------
// Launch
// ---------------------------------------------------------------------------
extern "C" void kernel_launch(void* const* d_in, const int* in_sizes, int n_in,
                              void* d_out, int out_size) {
    (void)in_sizes; (void)n_in; (void)out_size;
    const float* rgb   = (const float*)d_in[0];
    const float* pose  = (const float*)d_in[1];
    const float* Wq    = (const float*)d_in[2];
    const float* bq    = (const float*)d_in[3];
    const float* Wk    = (const float*)d_in[4];
    const float* bk    = (const float*)d_in[5];
    const float* Wv    = (const float*)d_in[6];
    const float* bv    = (const float*)d_in[7];
    const float* Wp    = (const float*)d_in[8];
    const float* bp    = (const float*)d_in[9];
    const float* gamma = (const float*)d_in[10];
    const float* beta  = (const float*)d_in[11];
    const float* gate  = (const float*)d_in[12];
    float* out = (float*)d_out;

    const int packin_blocks = (int)(((size_t)MROWS * (DIMP / 2) + 255) / 256);
    pack_in_kernel<<<dim3(packin_blocks, 2, 1), 256>>>(rgb, pose);
    pack_w_kernel<<<(3 * DIMP * HID + HID * DIM + 255) / 256, 256>>>(Wq, Wk, Wv, Wp);
    qkv_kernel<<<dim3(MROWS / 128, HID / 128, 3), 256>>>(bq, bk, bv);
    scores_kernel<<<dim3(SEQ / 128, SEQ / 128, NB), 256>>>();
    softmax_kernel<<<MROWS / 8, 256>>>();
    pv_kernel<<<dim3(SEQ / 128, HID / 128, NB), 256>>>();
    proj_kernel<<<dim3(MROWS / 128, (DIM + 127) / 128, 1), 256>>>(bp);
    ln_kernel<<<MROWS / 8, 256>>>(rgb, gamma, beta, gate, out);
}